// round 13
// baseline (speedup 1.0000x reference)
#include <cuda_runtime.h>
#include <math.h>

// Timewarp: B=64, C=128, T=4096, KNOT=4 -> n=6, h=819 (exact in f32)
#define NB 64
#define NC 128
#define NT 4096
#define NROW (NB*NC)
#define HF 819.0f
#define THREADS 256
#define QPT 16            // elements/queries per thread (256*16 = 4096)

struct SolveOp {
    float L[36];
    float U[36];
    int   piv[6];
};

// pair-index XOR swizzle for the float2 array: low4 ^= bits[4:8)
__device__ __forceinline__ int swzp(int i) { return i ^ ((i >> 4) & 15); }

__global__ __launch_bounds__(THREADS) void timewarp_kernel(
    const float* __restrict__ x,
    const float* __restrict__ yy,
    const float* __restrict__ mask_rand,
    float* __restrict__ out,
    SolveOp op)
{
    const int row = blockIdx.x;
    const int b = row >> 7;          // C = 128
    const int c = row & 127;
    const int tid = threadIdx.x;
    const int lane = tid & 31;
    const int wid = tid >> 5;

    const float* __restrict__ xrow = x + (size_t)row * NT;
    float* __restrict__ orow = out + (size_t)row * NT;

    // mask = mask_rand < 0.5 -> warped; else passthrough copy
    if (!(mask_rand[b] < 0.5f)) {
        const float4* src = (const float4*)xrow;
        float4* dst = (float4*)orow;
        #pragma unroll 4
        for (int j = tid; j < NT / 4; j += THREADS) dst[j] = src[j];
        return;
    }

    __shared__ float2 XF[4104];   // [0..4095] data, [4096..4097] sentinels; .x=xp .y=fp (swizzled)
    __shared__ float warpsum[8];
    __shared__ float P9s[8];
    __shared__ float Msh[6];
    __shared__ float Ysh[6];

    // ---- spline moments M on tid 0: f32 rhs + f32 LU solve (matches reference) ----
    if (tid == 0) {
        float yv[6];
        #pragma unroll
        for (int k = 0; k < 6; k++) {
            yv[k] = yy[((size_t)b * 6 + k) * NC + c];
            Ysh[k] = yv[k];
        }
        float rhs[6];
        rhs[0] = 0.0f; rhs[5] = 0.0f;
        #pragma unroll
        for (int i = 1; i <= 4; i++)
            rhs[i] = ((yv[i + 1] - 2.0f * yv[i]) + yv[i - 1]) / HF;

        float bb[6];
        #pragma unroll
        for (int i = 0; i < 6; i++) bb[i] = rhs[op.piv[i]];
        #pragma unroll
        for (int k = 0; k < 6; k++) {
            #pragma unroll
            for (int i = k + 1; i < 6; i++) bb[i] -= op.L[i * 6 + k] * bb[k];
        }
        #pragma unroll
        for (int k = 5; k >= 0; k--) {
            bb[k] = bb[k] / op.U[k * 6 + k];
            #pragma unroll
            for (int i = 0; i < k; i++) bb[i] -= op.U[i * 6 + k] * bb[k];
        }
        #pragma unroll
        for (int i = 0; i < 6; i++) Msh[i] = bb[i];

        XF[swzp(4096)].x = __int_as_float(0x7f800000);   // +inf sentinel (march stop)
        XF[swzp(4097)].x = __int_as_float(0x7f800000);   // +inf sentinel (prefetch slot)
    }
    __syncthreads();   // Msh/Ysh + sentinels visible

    // ---- curve for this thread's 16-element chunk (registers) ----
    // A 16-element chunk spans at most 2 knot intervals (819 > 16).
    const int base = tid * QPT;
    int s0 = base / 819;              if (s0 > 4) s0 = 4;
    int s1 = (base + QPT - 1) / 819;  if (s1 > 4) s1 = 4;
    const int tb = (s0 + 1) * 819;    // first t of second interval (if any)

    // hoisted per-interval constants (bitwise-identical to per-element computation)
    float Mi_a  = Msh[s0],     Mi1_a = Msh[s0 + 1];
    float a2_a  = Ysh[s0] / 819.0f     - (Mi_a  * 819.0f) / 6.0f;
    float a3_a  = Ysh[s0 + 1] / 819.0f - (Mi1_a * 819.0f) / 6.0f;
    int   x0_a  = s0 * 819;
    float Mi_b = Mi_a, Mi1_b = Mi1_a, a2_b = a2_a, a3_b = a3_a;
    int   x0_b = x0_a;
    if (s1 != s0) {
        Mi_b  = Msh[s1];  Mi1_b = Msh[s1 + 1];
        a2_b  = Ysh[s1] / 819.0f     - (Mi_b  * 819.0f) / 6.0f;
        a3_b  = Ysh[s1 + 1] / 819.0f - (Mi1_b * 819.0f) / 6.0f;
        x0_b  = s1 * 819;
    }

    const float INV4914 = 1.0f / 4914.0f;
    float r0[QPT];
    #pragma unroll
    for (int j = 0; j < QPT; j++) {
        int t = base + j;
        bool sb = (s1 != s0) && (t >= tb);
        float Mi  = sb ? Mi_b  : Mi_a;
        float Mi1 = sb ? Mi1_b : Mi1_a;
        float a2  = sb ? a2_b  : a2_a;
        float a3  = sb ? a3_b  : a3_a;
        int   x0  = sb ? x0_b  : x0_a;
        float dxl = (float)(t - x0);
        float dxr = (float)(x0 + 819 - t);
        float t1 = (Mi * ((dxr * dxr) * dxr) + Mi1 * ((dxl * dxl) * dxl)) * INV4914;
        r0[j] = (t1 + a2 * dxr) + a3 * dxl;
    }

    // ---- local up-sweep (levels 1..4) in registers ----
    float r1[8], r2[4], r3[2];
    #pragma unroll
    for (int k = 0; k < 8; k++) r1[k] = r0[2 * k] + r0[2 * k + 1];
    #pragma unroll
    for (int k = 0; k < 4; k++) r2[k] = r1[2 * k] + r1[2 * k + 1];
    #pragma unroll
    for (int k = 0; k < 2; k++) r3[k] = r2[2 * k] + r2[2 * k + 1];
    const float v4 = r3[0] + r3[1];

    // ---- warp up-sweep (levels 5..9) via shfl_xor; value valid on aligned lanes ----
    const unsigned FULL = 0xffffffffu;
    float v5 = v4 + __shfl_xor_sync(FULL, v4, 1);
    float v6 = v5 + __shfl_xor_sync(FULL, v5, 2);
    float v7 = v6 + __shfl_xor_sync(FULL, v6, 4);
    float v8 = v7 + __shfl_xor_sync(FULL, v7, 8);
    float v9 = v8 + __shfl_xor_sync(FULL, v8, 16);
    if (lane == 0) warpsum[wid] = v9;

    // ---- fp for this thread's own chunk -> registers (coalesced float4 reads).
    // Issued before the barrier so LDG latency overlaps the barrier wait and the
    // tid0 cross-warp scan. Values are bit-identical to the old shared scatter.
    const float4* fsrc = (const float4*)(xrow + base);
    float4 f4a = fsrc[0];
    float4 f4b = fsrc[1];
    float4 f4c = fsrc[2];
    float4 f4d = fsrc[3];

    __syncthreads();

    // ---- cross-warp levels 10..12 up + down to P9 (8 values), one thread ----
    if (tid == 0) {
        float r9[8];
        #pragma unroll
        for (int k = 0; k < 8; k++) r9[k] = warpsum[k];
        float r10[4];
        #pragma unroll
        for (int k = 0; k < 4; k++) r10[k] = r9[2 * k] + r9[2 * k + 1];
        float r11_0 = r10[0] + r10[1];
        float r11_1 = r10[2] + r10[3];
        float r12   = r11_0 + r11_1;
        float P11_0 = r11_0, P11_1 = r12;
        float P10_0 = r10[0];
        float P10_1 = P11_0;
        float P10_2 = P11_0 + r10[2];
        float P10_3 = P11_1;
        P9s[0] = r9[0];
        P9s[1] = P10_0;
        P9s[2] = P10_0 + r9[2];
        P9s[3] = P10_1;
        P9s[4] = P10_1 + r9[4];
        P9s[5] = P10_2;
        P9s[6] = P10_2 + r9[6];
        P9s[7] = P10_3;
    }
    __syncthreads();

    const bool w0 = (wid == 0);
    const float Ew  = w0 ? 0.0f : P9s[wid - 1];
    const float Pw  = P9s[wid];
    const float ttl = P9s[7];

    // ---- warp down-sweep (levels 8..4) via shfl, exact tree ----
    float v8_0  = __shfl_sync(FULL, v8, 0);
    float v7_0  = __shfl_sync(FULL, v7, 0);
    float v7_16 = __shfl_sync(FULL, v7, 16);
    float v6_0  = __shfl_sync(FULL, v6, 0);
    float v6_8  = __shfl_sync(FULL, v6, 8);
    float v6_16 = __shfl_sync(FULL, v6, 16);
    float v6_24 = __shfl_sync(FULL, v6, 24);

    float P8_0 = w0 ? v8_0 : Ew + v8_0;
    float P8_1 = Pw;
    float P7_0 = w0 ? v7_0 : Ew + v7_0;
    float P7_1 = P8_0;
    float P7_2 = P8_0 + v7_16;
    float P7_3 = P8_1;
    float P6_0 = w0 ? v6_0 : Ew + v6_0;
    float P6_1 = P7_0;
    float P6_2 = P7_0 + v6_8;
    float P6_3 = P7_1;
    float P6_4 = P7_1 + v6_16;
    float P6_5 = P7_2;
    float P6_6 = P7_2 + v6_24;
    float P6_7 = P7_3;

    int m6 = lane & 7;
    float p6 = P6_0;
    p6 = (m6 == 1) ? P6_1 : p6;
    p6 = (m6 == 2) ? P6_2 : p6;
    p6 = (m6 == 3) ? P6_3 : p6;
    p6 = (m6 == 4) ? P6_4 : p6;
    p6 = (m6 == 5) ? P6_5 : p6;
    p6 = (m6 == 6) ? P6_6 : p6;
    p6 = (m6 == 7) ? P6_7 : p6;

    int k5 = lane & 15;
    float r5k = __shfl_sync(FULL, v5, (k5 * 2) & 31);
    int idx6 = ((k5 & 1) ? (k5 >> 1) : ((k5 >> 1) - 1)) & 31;
    float p6k = __shfl_sync(FULL, p6, idx6);
    float p5;
    if (k5 == 0)       p5 = w0 ? r5k : Ew + r5k;
    else if (k5 & 1)   p5 = p6k;
    else               p5 = p6k + r5k;

    int idx5 = ((lane & 1) ? (lane >> 1) : ((lane >> 1) - 1)) & 31;
    float p5k = __shfl_sync(FULL, p5, idx5);
    float P4;
    if (lane == 0)     P4 = w0 ? v4 : Ew + v4;
    else if (lane & 1) P4 = p5k;
    else               P4 = p5k + v4;

    float E4 = __shfl_up_sync(FULL, P4, 1);
    if (lane == 0) E4 = Ew;
    const bool hasE = (tid > 0);
    const float E = E4;
    const float P4c = P4;

    // ---- local down-sweep (levels 3..0) in registers (exact tree) ----
    float P3_0 = hasE ? E + r3[0] : r3[0];
    float P3_1 = P4c;
    float P2_0 = hasE ? E + r2[0] : r2[0];
    float P2_1 = P3_0;
    float P2_2 = P3_0 + r2[2];
    float P2_3 = P3_1;
    float P1_0 = hasE ? E + r1[0] : r1[0];
    float P1_1 = P2_0;
    float P1_2 = P2_0 + r1[2];
    float P1_3 = P2_1;
    float P1_4 = P2_1 + r1[4];
    float P1_5 = P2_2;
    float P1_6 = P2_2 + r1[6];
    float P1_7 = P2_3;

    float tt[QPT];
    tt[0]  = hasE ? E + r0[0] : r0[0];
    tt[1]  = P1_0;
    tt[2]  = P1_0 + r0[2];  tt[3]  = P1_1;
    tt[4]  = P1_1 + r0[4];  tt[5]  = P1_2;
    tt[6]  = P1_2 + r0[6];  tt[7]  = P1_3;
    tt[8]  = P1_3 + r0[8];  tt[9]  = P1_4;
    tt[10] = P1_4 + r0[10]; tt[11] = P1_5;
    tt[12] = P1_5 + r0[12]; tt[13] = P1_6;
    tt[14] = P1_6 + r0[14]; tt[15] = P1_7;

    // ---- normalize (Markstein correctly-rounded division == exact '/') and
    //      FUSED xp+fp write: one STS.64 per element instead of two STS.32 ----
    {
        const float rc = 1.0f / ttl;          // one exact division per thread
        float fpv[QPT] = { f4a.x, f4a.y, f4a.z, f4a.w,
                           f4b.x, f4b.y, f4b.z, f4b.w,
                           f4c.x, f4c.y, f4c.z, f4c.w,
                           f4d.x, f4d.y, f4d.z, f4d.w };
        #pragma unroll
        for (int j = 0; j < QPT; j++) {
            float num = __fmul_rn(tt[j], 4095.0f);
            float q0  = __fmul_rn(num, rc);
            float r   = __fmaf_rn(-ttl, q0, num);
            float q   = __fmaf_rn(r, rc, q0);
            XF[swzp(base + j)] = make_float2(q, fpv[j]);
        }
    }
    __syncthreads();

    // ---- interp: one binary search + double-buffered monotone march ----
    const float2 e0 = XF[swzp(0)];
    const float2 eL = XF[swzp(4095)];
    const float xp0 = e0.x, fp0 = e0.y;
    const float xpL = eL.x, fpL = eL.y;

    float tf0 = (float)base;
    int lo = 0, hi = 4096;
    #pragma unroll
    for (int it = 0; it < 12; it++) {
        int mid = (lo + hi) >> 1;
        if (XF[swzp(mid)].x <= tf0) lo = mid + 1; else hi = mid;
    }
    int k = lo;

    float2 vprev = XF[swzp((k > 0) ? (k - 1) : 0)];
    float2 vcur  = XF[swzp(k)];           // k <= 4096; sentinel at 4096 is +inf
    float2 vnext = XF[swzp(k + 1)];       // prefetch (k+1 <= 4097, sentinel slot)

    const float EPSDX = 1.4210854715202004e-14f;   // np.spacing(eps_f32)
    float res[QPT];
    #pragma unroll
    for (int j = 0; j < QPT; j++) {
        float tf = (float)(base + j);
        while (vcur.x <= tf) {            // sentinel +inf bounds the march
            vprev = vcur;
            vcur  = vnext;
            ++k;
            vnext = XF[swzp(k + 1)];      // prefetched: chain is 1 load behind
        }
        float f;
        if (k >= 1 && k <= 4095) {
            float dx = vcur.x - vprev.x;
            f = (fabsf(dx) <= EPSDX) ? vprev.y
                : vprev.y + __fdividef(tf - vprev.x, dx) * (vcur.y - vprev.y);
        } else {
            int q = (k < 1) ? 1 : 4095;
            float2 a   = XF[swzp(q - 1)];
            float2 bb2 = XF[swzp(q)];
            float dx = bb2.x - a.x;
            f = (fabsf(dx) <= EPSDX) ? a.y
                : a.y + __fdividef(tf - a.x, dx) * (bb2.y - a.y);
        }
        if (tf < xp0) f = fp0;
        if (tf > xpL) f = fpL;
        res[j] = f;
    }

    // vector stores (each thread owns 16 consecutive outputs)
    float4* o4 = (float4*)(orow + base);
    #pragma unroll
    for (int q = 0; q < QPT / 4; q++)
        o4[q] = make_float4(res[4 * q + 0], res[4 * q + 1], res[4 * q + 2], res[4 * q + 3]);
}

// Host-side f32 partial-pivot LU of the fixed 6x6 not-a-knot matrix
static void build_solveop(SolveOp& op)
{
    float A[6][6];
    for (int i = 0; i < 6; i++)
        for (int j = 0; j < 6; j++) A[i][j] = 0.0f;
    const float h = 819.0f;
    for (int i = 1; i < 5; i++) {
        A[i][i - 1] = h / 6.0f;
        A[i][i]     = 2.0f * h / 3.0f;
        A[i][i + 1] = h / 6.0f;
    }
    A[0][0] = 1.0f; A[0][1] = -2.0f; A[0][2] = 1.0f;
    A[5][3] = 1.0f; A[5][4] = -2.0f; A[5][5] = 1.0f;

    int piv[6] = {0, 1, 2, 3, 4, 5};
    for (int k = 0; k < 6; k++) {
        int p = k; float mx = fabsf(A[k][k]);
        for (int i = k + 1; i < 6; i++) {
            float v = fabsf(A[i][k]);
            if (v > mx) { mx = v; p = i; }
        }
        if (p != k) {
            for (int j = 0; j < 6; j++) { float tm = A[k][j]; A[k][j] = A[p][j]; A[p][j] = tm; }
            int tp = piv[k]; piv[k] = piv[p]; piv[p] = tp;
        }
        float r = 1.0f / A[k][k];
        for (int i = k + 1; i < 6; i++) {
            A[i][k] = A[i][k] * r;
            for (int j = k + 1; j < 6; j++)
                A[i][j] = A[i][j] - A[i][k] * A[k][j];
        }
    }
    for (int i = 0; i < 6; i++) {
        for (int j = 0; j < 6; j++) {
            op.L[i * 6 + j] = (j < i) ? A[i][j] : (i == j ? 1.0f : 0.0f);
            op.U[i * 6 + j] = (j >= i) ? A[i][j] : 0.0f;
        }
        op.piv[i] = piv[i];
    }
}

extern "C" void kernel_launch(void* const* d_in, const int* in_sizes, int n_in,
                              void* d_out, int out_size)
{
    (void)in_sizes; (void)n_in; (void)out_size;
    const float* x         = (const float*)d_in[0];
    const float* yy        = (const float*)d_in[1];
    const float* mask_rand = (const float*)d_in[2];
    float* out = (float*)d_out;

    SolveOp op;
    build_solveop(op);

    timewarp_kernel<<<NROW, THREADS>>>(x, yy, mask_rand, out, op);
}

// round 14
// speedup vs baseline: 1.0637x; 1.0637x over previous
#include <cuda_runtime.h>
#include <math.h>

// Timewarp: B=64, C=128, T=4096, KNOT=4 -> n=6, h=819 (exact in f32)
#define NB 64
#define NC 128
#define NT 4096
#define NROW (NB*NC)
#define HF 819.0f
#define THREADS 256
#define QPT 16            // elements/queries per thread (256*16 = 4096)

struct SolveOp {
    float L[36];
    float U[36];
    int   piv[6];
};

// pair-index XOR swizzle for the float2 array: low4 ^= bits[4:8)
__device__ __forceinline__ int swzp(int i) { return i ^ ((i >> 4) & 15); }

__global__ __launch_bounds__(THREADS) void timewarp_kernel(
    const float* __restrict__ x,
    const float* __restrict__ yy,
    const float* __restrict__ mask_rand,
    float* __restrict__ out,
    SolveOp op)
{
    const int row = blockIdx.x;
    const int b = row >> 7;          // C = 128
    const int c = row & 127;
    const int tid = threadIdx.x;
    const int lane = tid & 31;
    const int wid = tid >> 5;

    const float* __restrict__ xrow = x + (size_t)row * NT;
    float* __restrict__ orow = out + (size_t)row * NT;

    // mask = mask_rand < 0.5 -> warped; else passthrough copy
    if (!(mask_rand[b] < 0.5f)) {
        const float4* src = (const float4*)xrow;
        float4* dst = (float4*)orow;
        #pragma unroll 4
        for (int j = tid; j < NT / 4; j += THREADS) dst[j] = src[j];
        return;
    }

    __shared__ float2 XF[4104];   // [0..4095] data, [4096..4097] sentinels; .x=xp .y=fp (swizzled)
    __shared__ float warpsum[8];
    __shared__ float P9s[8];
    __shared__ float Msh[6];
    __shared__ float Ysh[6];

    // ---- spline moments M on tid 0: f32 rhs + f32 LU solve (matches reference) ----
    if (tid == 0) {
        float yv[6];
        #pragma unroll
        for (int k = 0; k < 6; k++) {
            yv[k] = yy[((size_t)b * 6 + k) * NC + c];
            Ysh[k] = yv[k];
        }
        float rhs[6];
        rhs[0] = 0.0f; rhs[5] = 0.0f;
        #pragma unroll
        for (int i = 1; i <= 4; i++)
            rhs[i] = ((yv[i + 1] - 2.0f * yv[i]) + yv[i - 1]) / HF;

        float bb[6];
        #pragma unroll
        for (int i = 0; i < 6; i++) bb[i] = rhs[op.piv[i]];
        #pragma unroll
        for (int k = 0; k < 6; k++) {
            #pragma unroll
            for (int i = k + 1; i < 6; i++) bb[i] -= op.L[i * 6 + k] * bb[k];
        }
        #pragma unroll
        for (int k = 5; k >= 0; k--) {
            bb[k] = bb[k] / op.U[k * 6 + k];
            #pragma unroll
            for (int i = 0; i < k; i++) bb[i] -= op.U[i * 6 + k] * bb[k];
        }
        #pragma unroll
        for (int i = 0; i < 6; i++) Msh[i] = bb[i];

        XF[swzp(4096)].x = __int_as_float(0x7f800000);   // +inf sentinel (march stop)
        XF[swzp(4097)].x = __int_as_float(0x7f800000);   // +inf sentinel (prefetch slot)
    }
    __syncthreads();   // Msh/Ysh + sentinels visible

    // ---- curve for this thread's 16-element chunk (registers) ----
    // A 16-element chunk spans at most 2 knot intervals (819 > 16).
    const int base = tid * QPT;
    int s0 = base / 819;              if (s0 > 4) s0 = 4;
    int s1 = (base + QPT - 1) / 819;  if (s1 > 4) s1 = 4;
    const int tb = (s0 + 1) * 819;    // first t of second interval (if any)

    // hoisted per-interval constants (bitwise-identical to per-element computation)
    float Mi_a  = Msh[s0],     Mi1_a = Msh[s0 + 1];
    float a2_a  = Ysh[s0] / 819.0f     - (Mi_a  * 819.0f) / 6.0f;
    float a3_a  = Ysh[s0 + 1] / 819.0f - (Mi1_a * 819.0f) / 6.0f;
    int   x0_a  = s0 * 819;
    float Mi_b = Mi_a, Mi1_b = Mi1_a, a2_b = a2_a, a3_b = a3_a;
    int   x0_b = x0_a;
    if (s1 != s0) {
        Mi_b  = Msh[s1];  Mi1_b = Msh[s1 + 1];
        a2_b  = Ysh[s1] / 819.0f     - (Mi_b  * 819.0f) / 6.0f;
        a3_b  = Ysh[s1 + 1] / 819.0f - (Mi1_b * 819.0f) / 6.0f;
        x0_b  = s1 * 819;
    }

    const float INV4914 = 1.0f / 4914.0f;
    float r0[QPT];
    #pragma unroll
    for (int j = 0; j < QPT; j++) {
        int t = base + j;
        bool sb = (s1 != s0) && (t >= tb);
        float Mi  = sb ? Mi_b  : Mi_a;
        float Mi1 = sb ? Mi1_b : Mi1_a;
        float a2  = sb ? a2_b  : a2_a;
        float a3  = sb ? a3_b  : a3_a;
        int   x0  = sb ? x0_b  : x0_a;
        float dxl = (float)(t - x0);
        float dxr = (float)(x0 + 819 - t);
        float t1 = (Mi * ((dxr * dxr) * dxr) + Mi1 * ((dxl * dxl) * dxl)) * INV4914;
        r0[j] = (t1 + a2 * dxr) + a3 * dxl;
    }

    // ---- local up-sweep (levels 1..4) in registers ----
    float r1[8], r2[4], r3[2];
    #pragma unroll
    for (int k = 0; k < 8; k++) r1[k] = r0[2 * k] + r0[2 * k + 1];
    #pragma unroll
    for (int k = 0; k < 4; k++) r2[k] = r1[2 * k] + r1[2 * k + 1];
    #pragma unroll
    for (int k = 0; k < 2; k++) r3[k] = r2[2 * k] + r2[2 * k + 1];
    const float v4 = r3[0] + r3[1];

    // ---- warp up-sweep (levels 5..9) via shfl_xor; value valid on aligned lanes ----
    const unsigned FULL = 0xffffffffu;
    float v5 = v4 + __shfl_xor_sync(FULL, v4, 1);
    float v6 = v5 + __shfl_xor_sync(FULL, v5, 2);
    float v7 = v6 + __shfl_xor_sync(FULL, v6, 4);
    float v8 = v7 + __shfl_xor_sync(FULL, v7, 8);
    float v9 = v8 + __shfl_xor_sync(FULL, v8, 16);
    if (lane == 0) warpsum[wid] = v9;
    __syncthreads();

    // ---- cross-warp levels 10..12 up + down to P9 (8 values), one thread ----
    if (tid == 0) {
        float r9[8];
        #pragma unroll
        for (int k = 0; k < 8; k++) r9[k] = warpsum[k];
        float r10[4];
        #pragma unroll
        for (int k = 0; k < 4; k++) r10[k] = r9[2 * k] + r9[2 * k + 1];
        float r11_0 = r10[0] + r10[1];
        float r11_1 = r10[2] + r10[3];
        float r12   = r11_0 + r11_1;
        float P11_0 = r11_0, P11_1 = r12;
        float P10_0 = r10[0];
        float P10_1 = P11_0;
        float P10_2 = P11_0 + r10[2];
        float P10_3 = P11_1;
        P9s[0] = r9[0];
        P9s[1] = P10_0;
        P9s[2] = P10_0 + r9[2];
        P9s[3] = P10_1;
        P9s[4] = P10_1 + r9[4];
        P9s[5] = P10_2;
        P9s[6] = P10_2 + r9[6];
        P9s[7] = P10_3;
    }
    __syncthreads();

    const bool w0 = (wid == 0);
    const float Ew  = w0 ? 0.0f : P9s[wid - 1];
    const float Pw  = P9s[wid];
    const float ttl = P9s[7];

    // ---- warp down-sweep (levels 8..4) via shfl, exact tree ----
    float v8_0  = __shfl_sync(FULL, v8, 0);
    float v7_0  = __shfl_sync(FULL, v7, 0);
    float v7_16 = __shfl_sync(FULL, v7, 16);
    float v6_0  = __shfl_sync(FULL, v6, 0);
    float v6_8  = __shfl_sync(FULL, v6, 8);
    float v6_16 = __shfl_sync(FULL, v6, 16);
    float v6_24 = __shfl_sync(FULL, v6, 24);

    float P8_0 = w0 ? v8_0 : Ew + v8_0;
    float P8_1 = Pw;
    float P7_0 = w0 ? v7_0 : Ew + v7_0;
    float P7_1 = P8_0;
    float P7_2 = P8_0 + v7_16;
    float P7_3 = P8_1;
    float P6_0 = w0 ? v6_0 : Ew + v6_0;
    float P6_1 = P7_0;
    float P6_2 = P7_0 + v6_8;
    float P6_3 = P7_1;
    float P6_4 = P7_1 + v6_16;
    float P6_5 = P7_2;
    float P6_6 = P7_2 + v6_24;
    float P6_7 = P7_3;

    int m6 = lane & 7;
    float p6 = P6_0;
    p6 = (m6 == 1) ? P6_1 : p6;
    p6 = (m6 == 2) ? P6_2 : p6;
    p6 = (m6 == 3) ? P6_3 : p6;
    p6 = (m6 == 4) ? P6_4 : p6;
    p6 = (m6 == 5) ? P6_5 : p6;
    p6 = (m6 == 6) ? P6_6 : p6;
    p6 = (m6 == 7) ? P6_7 : p6;

    int k5 = lane & 15;
    float r5k = __shfl_sync(FULL, v5, (k5 * 2) & 31);
    int idx6 = ((k5 & 1) ? (k5 >> 1) : ((k5 >> 1) - 1)) & 31;
    float p6k = __shfl_sync(FULL, p6, idx6);
    float p5;
    if (k5 == 0)       p5 = w0 ? r5k : Ew + r5k;
    else if (k5 & 1)   p5 = p6k;
    else               p5 = p6k + r5k;

    int idx5 = ((lane & 1) ? (lane >> 1) : ((lane >> 1) - 1)) & 31;
    float p5k = __shfl_sync(FULL, p5, idx5);
    float P4;
    if (lane == 0)     P4 = w0 ? v4 : Ew + v4;
    else if (lane & 1) P4 = p5k;
    else               P4 = p5k + v4;

    float E4 = __shfl_up_sync(FULL, P4, 1);
    if (lane == 0) E4 = Ew;
    const bool hasE = (tid > 0);
    const float E = E4;
    const float P4c = P4;

    // ---- local down-sweep (levels 3..0) in registers (exact tree) ----
    float P3_0 = hasE ? E + r3[0] : r3[0];
    float P3_1 = P4c;
    float P2_0 = hasE ? E + r2[0] : r2[0];
    float P2_1 = P3_0;
    float P2_2 = P3_0 + r2[2];
    float P2_3 = P3_1;
    float P1_0 = hasE ? E + r1[0] : r1[0];
    float P1_1 = P2_0;
    float P1_2 = P2_0 + r1[2];
    float P1_3 = P2_1;
    float P1_4 = P2_1 + r1[4];
    float P1_5 = P2_2;
    float P1_6 = P2_2 + r1[6];
    float P1_7 = P2_3;

    float tt[QPT];
    tt[0]  = hasE ? E + r0[0] : r0[0];
    tt[1]  = P1_0;
    tt[2]  = P1_0 + r0[2];  tt[3]  = P1_1;
    tt[4]  = P1_1 + r0[4];  tt[5]  = P1_2;
    tt[6]  = P1_2 + r0[6];  tt[7]  = P1_3;
    tt[8]  = P1_3 + r0[8];  tt[9]  = P1_4;
    tt[10] = P1_4 + r0[10]; tt[11] = P1_5;
    tt[12] = P1_5 + r0[12]; tt[13] = P1_6;
    tt[14] = P1_6 + r0[14]; tt[15] = P1_7;

    // ---- normalize (Markstein correctly-rounded division == exact '/') and
    //      FUSED xp+fp write (STS.64), fp loaded JUST-IN-TIME per float4 group
    //      so its register lifetime is ~one group (avoids the R13 reg blowup) ----
    {
        const float rc = 1.0f / ttl;          // one exact division per thread
        const float4* fsrc = (const float4*)(xrow + base);
        #pragma unroll
        for (int g = 0; g < QPT / 4; g++) {
            float4 f4 = fsrc[g];              // coalesced LDG.128, consumed immediately
            #pragma unroll
            for (int jj = 0; jj < 4; jj++) {
                int j = 4 * g + jj;
                float fpv = (jj == 0) ? f4.x : (jj == 1) ? f4.y : (jj == 2) ? f4.z : f4.w;
                float num = __fmul_rn(tt[j], 4095.0f);
                float q0  = __fmul_rn(num, rc);
                float r   = __fmaf_rn(-ttl, q0, num);
                float q   = __fmaf_rn(r, rc, q0);
                XF[swzp(base + j)] = make_float2(q, fpv);
            }
        }
    }
    __syncthreads();

    // ---- interp: one binary search + double-buffered monotone march ----
    const float2 e0 = XF[swzp(0)];
    const float2 eL = XF[swzp(4095)];
    const float xp0 = e0.x, fp0 = e0.y;
    const float xpL = eL.x, fpL = eL.y;

    float tf0 = (float)base;
    int lo = 0, hi = 4096;
    #pragma unroll
    for (int it = 0; it < 12; it++) {
        int mid = (lo + hi) >> 1;
        if (XF[swzp(mid)].x <= tf0) lo = mid + 1; else hi = mid;
    }
    int k = lo;

    float2 vprev = XF[swzp((k > 0) ? (k - 1) : 0)];
    float2 vcur  = XF[swzp(k)];           // k <= 4096; sentinel at 4096 is +inf
    float2 vnext = XF[swzp(k + 1)];       // prefetch (k+1 <= 4097, sentinel slot)

    const float EPSDX = 1.4210854715202004e-14f;   // np.spacing(eps_f32)
    float res[QPT];
    #pragma unroll
    for (int j = 0; j < QPT; j++) {
        float tf = (float)(base + j);
        while (vcur.x <= tf) {            // sentinel +inf bounds the march
            vprev = vcur;
            vcur  = vnext;
            ++k;
            vnext = XF[swzp(k + 1)];      // prefetched: chain is 1 load behind
        }
        float f;
        if (k >= 1 && k <= 4095) {
            float dx = vcur.x - vprev.x;
            f = (fabsf(dx) <= EPSDX) ? vprev.y
                : vprev.y + __fdividef(tf - vprev.x, dx) * (vcur.y - vprev.y);
        } else {
            int q = (k < 1) ? 1 : 4095;
            float2 a   = XF[swzp(q - 1)];
            float2 bb2 = XF[swzp(q)];
            float dx = bb2.x - a.x;
            f = (fabsf(dx) <= EPSDX) ? a.y
                : a.y + __fdividef(tf - a.x, dx) * (bb2.y - a.y);
        }
        if (tf < xp0) f = fp0;
        if (tf > xpL) f = fpL;
        res[j] = f;
    }

    // vector stores (each thread owns 16 consecutive outputs)
    float4* o4 = (float4*)(orow + base);
    #pragma unroll
    for (int q = 0; q < QPT / 4; q++)
        o4[q] = make_float4(res[4 * q + 0], res[4 * q + 1], res[4 * q + 2], res[4 * q + 3]);
}

// Host-side f32 partial-pivot LU of the fixed 6x6 not-a-knot matrix
static void build_solveop(SolveOp& op)
{
    float A[6][6];
    for (int i = 0; i < 6; i++)
        for (int j = 0; j < 6; j++) A[i][j] = 0.0f;
    const float h = 819.0f;
    for (int i = 1; i < 5; i++) {
        A[i][i - 1] = h / 6.0f;
        A[i][i]     = 2.0f * h / 3.0f;
        A[i][i + 1] = h / 6.0f;
    }
    A[0][0] = 1.0f; A[0][1] = -2.0f; A[0][2] = 1.0f;
    A[5][3] = 1.0f; A[5][4] = -2.0f; A[5][5] = 1.0f;

    int piv[6] = {0, 1, 2, 3, 4, 5};
    for (int k = 0; k < 6; k++) {
        int p = k; float mx = fabsf(A[k][k]);
        for (int i = k + 1; i < 6; i++) {
            float v = fabsf(A[i][k]);
            if (v > mx) { mx = v; p = i; }
        }
        if (p != k) {
            for (int j = 0; j < 6; j++) { float tm = A[k][j]; A[k][j] = A[p][j]; A[p][j] = tm; }
            int tp = piv[k]; piv[k] = piv[p]; piv[p] = tp;
        }
        float r = 1.0f / A[k][k];
        for (int i = k + 1; i < 6; i++) {
            A[i][k] = A[i][k] * r;
            for (int j = k + 1; j < 6; j++)
                A[i][j] = A[i][j] - A[i][k] * A[k][j];
        }
    }
    for (int i = 0; i < 6; i++) {
        for (int j = 0; j < 6; j++) {
            op.L[i * 6 + j] = (j < i) ? A[i][j] : (i == j ? 1.0f : 0.0f);
            op.U[i * 6 + j] = (j >= i) ? A[i][j] : 0.0f;
        }
        op.piv[i] = piv[i];
    }
}

extern "C" void kernel_launch(void* const* d_in, const int* in_sizes, int n_in,
                              void* d_out, int out_size)
{
    (void)in_sizes; (void)n_in; (void)out_size;
    const float* x         = (const float*)d_in[0];
    const float* yy        = (const float*)d_in[1];
    const float* mask_rand = (const float*)d_in[2];
    float* out = (float*)d_out;

    SolveOp op;
    build_solveop(op);

    timewarp_kernel<<<NROW, THREADS>>>(x, yy, mask_rand, out, op);
}